// round 3
// baseline (speedup 1.0000x reference)
#include <cuda_runtime.h>

#define THREADS 256
#define OPT 8
#define TILE (THREADS * OPT)      // 2048 outputs per block
#define KMAX 64                   // taps padded to 64 (zeros)
#define SMEM_U (TILE + KMAX)      // 2112 floats
#define NQUAD (SMEM_U / 4)        // 528

typedef unsigned long long ull;

__device__ __forceinline__ ull pk2(float lo, float hi) {
    ull r; asm("mov.b64 %0, {%1, %2};" : "=l"(r) : "f"(lo), "f"(hi)); return r;
}
__device__ __forceinline__ void upk2(ull v, float& lo, float& hi) {
    asm("mov.b64 {%0, %1}, %2;" : "=f"(lo), "=f"(hi) : "l"(v));
}
__device__ __forceinline__ ull ffma2(ull a, ull b, ull c) {
    ull d; asm("fma.rn.f32x2 %0, %1, %2, %3;" : "=l"(d) : "l"(a), "l"(b), "l"(c)); return d;
}

__global__ __launch_bounds__(THREADS) void fir2_kernel(
    const float* __restrict__ u, const float* __restrict__ kern,
    float* __restrict__ out, int cols, int out_cols, int K)
{
    __shared__ float s_u[SMEM_U];
    __shared__ float2 s_w2[KMAX];         // splatted weight pairs (w, w)

    const int tid  = threadIdx.x;
    const int row  = blockIdx.y;
    const int base = blockIdx.x * TILE;
    const float* urow = u + (size_t)row * cols;

    // Reversed, splatted, zero-padded weight pairs.
    if (tid < KMAX) {
        const float w = (tid < K) ? kern[K - 1 - tid] : 0.0f;
        s_w2[tid] = make_float2(w, w);
    }

    // Stage input tile (coalesced float4, zero-fill past end of row).
    for (int q = tid; q < NQUAD; q += THREADS) {
        const int gi = base + q * 4;
        float4 v;
        if (gi + 3 < cols) {
            v = *reinterpret_cast<const float4*>(urow + gi);
        } else {
            v.x = (gi + 0 < cols) ? urow[gi + 0] : 0.0f;
            v.y = (gi + 1 < cols) ? urow[gi + 1] : 0.0f;
            v.z = (gi + 2 < cols) ? urow[gi + 2] : 0.0f;
            v.w = (gi + 3 < cols) ? urow[gi + 3] : 0.0f;
        }
        reinterpret_cast<float4*>(s_u)[q] = v;
    }
    __syncthreads();

    const float4*     su4 = reinterpret_cast<const float4*>(s_u);
    const ulonglong2* sw4 = reinterpret_cast<const ulonglong2*>(s_w2);

    // Sliding window: win[0..11] = v[4m .. 4m+11] (thread-local indices).
    float win[12];
    {
        const float4 a = su4[tid * 2 + 0];
        const float4 b = su4[tid * 2 + 1];
        win[0]=a.x; win[1]=a.y; win[2]=a.z; win[3]=a.w;
        win[4]=b.x; win[5]=b.y; win[6]=b.z; win[7]=b.w;
    }

    ull A0 = 0ull, A1 = 0ull, A2 = 0ull, A3 = 0ull;   // (o0,o1)(o2,o3)(o4,o5)(o6,o7)

    #pragma unroll
    for (int m = 0; m < KMAX / 4; ++m) {              // 4 taps per iteration
        const float4 nq = su4[tid * 2 + m + 2];       // conflict-free (consecutive quads)
        win[8]=nq.x; win[9]=nq.y; win[10]=nq.z; win[11]=nq.w;

        const ulonglong2 Wab = sw4[2 * m + 0];        // splat pairs for taps 4m, 4m+1 (broadcast)
        const ulonglong2 Wcd = sw4[2 * m + 1];        // taps 4m+2, 4m+3

        #pragma unroll
        for (int t = 0; t < 4; ++t) {
            const ull W = (t == 0) ? Wab.x : (t == 1) ? Wab.y : (t == 2) ? Wcd.x : Wcd.y;
            A0 = ffma2(pk2(win[t + 0], win[t + 1]), W, A0);
            A1 = ffma2(pk2(win[t + 2], win[t + 3]), W, A1);
            A2 = ffma2(pk2(win[t + 4], win[t + 5]), W, A2);
            A3 = ffma2(pk2(win[t + 6], win[t + 7]), W, A3);
        }

        #pragma unroll
        for (int k = 0; k < 8; ++k) win[k] = win[k + 4];   // renamed away by unroll
    }

    float o0,o1,o2,o3,o4,o5,o6,o7;
    upk2(A0, o0, o1); upk2(A1, o2, o3); upk2(A2, o4, o5); upk2(A3, o6, o7);

    const int oc = base + tid * OPT;
    float* orow = out + (size_t)row * out_cols;
    if (oc + 7 < out_cols) {
        float4 r0; r0.x=o0; r0.y=o1; r0.z=o2; r0.w=o3;
        float4 r1; r1.x=o4; r1.y=o5; r1.z=o6; r1.w=o7;
        *reinterpret_cast<float4*>(orow + oc + 0) = r0;
        *reinterpret_cast<float4*>(orow + oc + 4) = r1;
    } else {
        if (oc + 0 < out_cols) orow[oc + 0] = o0;
        if (oc + 1 < out_cols) orow[oc + 1] = o1;
        if (oc + 2 < out_cols) orow[oc + 2] = o2;
        if (oc + 3 < out_cols) orow[oc + 3] = o3;
        if (oc + 4 < out_cols) orow[oc + 4] = o4;
        if (oc + 5 < out_cols) orow[oc + 5] = o5;
        if (oc + 6 < out_cols) orow[oc + 6] = o6;
        if (oc + 7 < out_cols) orow[oc + 7] = o7;
    }
}

extern "C" void kernel_launch(void* const* d_in, const int* in_sizes, int n_in,
                              void* d_out, int out_size)
{
    const float* u    = (const float*)d_in[0];
    const float* kern = (const float*)d_in[1];
    float*       out  = (float*)d_out;

    const int S0 = in_sizes[0];
    const int K  = in_sizes[1];
    const int rows     = (S0 - out_size) / (K - 1);
    const int cols     = S0 / rows;
    const int out_cols = cols - K + 1;

    dim3 grid((out_cols + TILE - 1) / TILE, rows);
    fir2_kernel<<<grid, THREADS>>>(u, kern, out, cols, out_cols, K);
}